// round 2
// baseline (speedup 1.0000x reference)
#include <cuda_runtime.h>
#include <math.h>

#define B_   2
#define P_   8192
#define NB_  24
#define C1_  32
#define C2_  32
#define K_   13
#define A_   12
#define CA_  384            // c1 * A
#define NDR_ 384            // C2 * A (n = r*32 + d)
#define TP_  32             // points per block
#define CC_  32             // ca chunk
#define NCH_ 12             // CA_/CC_
#define STEPS_ (K_*NCH_)    // 156

// -------- device scratch (no allocations allowed) --------
__device__ __align__(16) float g_WT[K_*CA_*NDR_];   // [k][ca][r*32+d]  (~7.7MB)
__device__ __align__(16) float g_md[B_*P_*3];       // mean_dir
__device__ __align__(16) float g_kpo[C2_*K_*3];     // normalized k_pos_ori
__device__ __align__(16) float g_be[C2_*A_];        // bias_eff[d][r]

// -------- prep: k_pos_ori + bias_eff --------
__global__ void prep_small(const float* __restrict__ kpw, const float* __restrict__ vs,
                           const int* __restrict__ idx_map, const float* __restrict__ bias,
                           const int* __restrict__ lvl, const int* __restrict__ tivr) {
    int tid = threadIdx.x;
    if (tid < C2_*K_) {
        int d = tid / K_, k = tid % K_;
        float s0 = 0.f, s1 = 0.f, s2 = 0.f;
        for (int a = 0; a < A_; a++) {
            float w = kpw[d*36 + idx_map[k*A_ + a]];
            s0 += w * vs[a*3+0];
            s1 += w * vs[a*3+1];
            s2 += w * vs[a*3+2];
        }
        float nm = sqrtf(s0*s0 + s1*s1 + s2*s2);
        float inv = 1.0f / fmaxf(nm, 1e-12f);
        g_kpo[tid*3+0] = s0*inv;
        g_kpo[tid*3+1] = s1*inv;
        g_kpo[tid*3+2] = s2*inv;
    }
    if (tid < C2_*A_) {
        int d = tid / A_, r = tid % A_;
        float be = 0.f;
        for (int k = 0; k < K_; k++) be += bias[d*5 + lvl[tivr[r*K_ + k]]];
        g_be[tid] = be;
    }
}

// -------- prep: WT[d,c,k,a,r] -> g_WT[k][c*12+a][r*32+d] --------
__global__ void prep_wt(const float* __restrict__ W, const float* __restrict__ kpw,
                        const int* __restrict__ idx_map, const int* __restrict__ tivr,
                        const int* __restrict__ tir) {
    int idx = blockIdx.x * blockDim.x + threadIdx.x;
    if (idx >= K_*CA_*NDR_) return;
    int k   = idx / (CA_*NDR_);
    int rem = idx - k*(CA_*NDR_);
    int ca  = rem / NDR_;
    int n   = rem - ca*NDR_;
    int c = ca / A_, a = ca - c*A_;
    int r = n >> 5, d = n & 31;
    int m = idx_map[tivr[r*K_ + k]*A_ + tir[r*A_ + a]];
    g_WT[idx] = W[(d*C1_ + c)*36 + m] * kpw[d*36 + m];
}

// -------- prep: mean of normalized neighbor directions --------
__global__ void mean_dir_kernel(const int* __restrict__ nbr, const float* __restrict__ vert) {
    int t = blockIdx.x * blockDim.x + threadIdx.x;
    if (t >= B_*P_) return;
    int b = t / P_;
    float vx = vert[t*3+0], vy = vert[t*3+1], vz = vert[t*3+2];
    float mx = 0.f, my = 0.f, mz = 0.f;
    const int* np = nbr + (size_t)t * NB_;
    const float* vb = vert + (size_t)b * P_ * 3;
    #pragma unroll 4
    for (int n = 0; n < NB_; n++) {
        int q = np[n];
        float dx = vb[q*3+0] - vx;
        float dy = vb[q*3+1] - vy;
        float dz = vb[q*3+2] - vz;
        float nm = sqrtf(dx*dx + dy*dy + dz*dz);
        float inv = 1.0f / fmaxf(nm, 1e-12f);
        mx += dx*inv; my += dy*inv; mz += dz*inv;
    }
    const float s = 1.0f / (float)NB_;
    g_md[t*3+0] = mx*s; g_md[t*3+1] = my*s; g_md[t*3+2] = mz*s;
}

// -------- cp.async helper --------
__device__ __forceinline__ void cp16(float* dst, const float* src) {
    unsigned a = (unsigned)__cvta_generic_to_shared(dst);
    asm volatile("cp.async.cg.shared.global [%0], [%1], 16;" :: "r"(a), "l"(src));
}

// -------- main fused kernel --------
// grid = 512 (b * 256 p-tiles), block = 256 threads.
// thread (d = tid&31, gp = tid>>5) computes 4 points x 12 r for its d.
__global__ void __launch_bounds__(256, 1)
main_kernel(const float* __restrict__ fm, float* __restrict__ out) {
    extern __shared__ float sm[];
    float* sFM  = sm;                       // [2][TP_][CA_]   96KB, row = point (1536B)
    float* sB   = sm + 2*TP_*CA_;           // [2][CC_][NDR_]  96KB
    float* sKPO = sB + 2*CC_*NDR_;          // [C2_*K_*3]

    const int tid = threadIdx.x;
    const int d   = tid & 31;
    const int gp  = tid >> 5;               // warp id = p-group
    const int b   = blockIdx.x >> 8;        // 256 p-tiles per batch
    const int p0  = (blockIdx.x & 255) * TP_;
    const float* fmB = fm + (size_t)b * C1_ * K_ * P_ * A_;

    for (int i = tid; i < C2_*K_*3; i += 256) sKPO[i] = g_kpo[i];

    float md[4][3];
    #pragma unroll
    for (int i = 0; i < 4; i++) {
        int p = p0 + 4*gp + i;
        const float* mp = g_md + ((size_t)b*P_ + p)*3;
        md[i][0] = mp[0]; md[i][1] = mp[1]; md[i][2] = mp[2];
    }

    float acc[4][12];
    #pragma unroll
    for (int i = 0; i < 4; i++)
        #pragma unroll
        for (int r = 0; r < 12; r++) acc[i][r] = 0.f;

    // loaders: fm tile (32 pts x 384 ca) and WT chunk (32 ca x 384 n)
    auto fm_load = [&](int k, int buf) {
        float* base = sFM + buf*TP_*CA_;
        #pragma unroll
        for (int j = 0; j < 12; j++) {
            int t  = tid + 256*j;              // 0..3071 16B-chunks
            int c  = t / 96;                   // 96 chunks per c (32 pp x 3 aq)
            int rm = t - c*96;
            int pp = rm / 3;
            int aq = rm - pp*3;
            const float* src = fmB + ((size_t)(c*K_ + k)*P_ + (p0 + pp))*A_ + aq*4;
            cp16(base + pp*CA_ + c*A_ + aq*4, src);
        }
    };
    auto b_load = [&](int k, int cc, int buf) {
        const float* src = g_WT + ((size_t)k*CA_ + cc*CC_)*NDR_;
        float* dst = sB + buf*CC_*NDR_;
        #pragma unroll
        for (int j = 0; j < 12; j++) {
            int t = (tid + 256*j) * 4;
            cp16(dst + t, src + t);
        }
    };

    __syncthreads();                           // sKPO visible

    fm_load(0, 0);
    b_load(0, 0, 0);
    asm volatile("cp.async.commit_group;" ::: "memory");

    int s = 0;
    for (int k = 0; k < K_; k++) {
        const float* kp = sKPO + (d*K_ + k)*3;
        float pwv[4];
        #pragma unroll
        for (int i = 0; i < 4; i++) {
            float v = md[i][0]*kp[0] + md[i][1]*kp[1] + md[i][2]*kp[2];
            pwv[i] = fmaxf(v, 0.0f);
        }
        float part[4][12];
        #pragma unroll
        for (int i = 0; i < 4; i++)
            #pragma unroll
            for (int r = 0; r < 12; r++) part[i][r] = 0.f;

        const int fbuf = k & 1;
        for (int cc = 0; cc < NCH_; cc++) {
            asm volatile("cp.async.wait_group 0;" ::: "memory");
            __syncthreads();

            const int ns = s + 1;
            if (ns < STEPS_) {
                const int nk  = ns / NCH_;
                const int ncc = ns - nk*NCH_;
                b_load(nk, ncc, ns & 1);
                if (ncc == 0) fm_load(nk, nk & 1);
            }
            asm volatile("cp.async.commit_group;" ::: "memory");

            const float* Af = sFM + fbuf*TP_*CA_ + (4*gp)*CA_ + cc*CC_;  // broadcast reads
            const float* Bf = sB  + (s & 1)*CC_*NDR_ + d;                // lane-consecutive

            #pragma unroll 8
            for (int i = 0; i < CC_; i++) {
                float a0 = Af[i];
                float a1 = Af[CA_ + i];
                float a2 = Af[2*CA_ + i];
                float a3 = Af[3*CA_ + i];
                const float* br = Bf + i*NDR_;
                #pragma unroll
                for (int r = 0; r < 12; r++) {
                    float bv = br[r*32];
                    part[0][r] = fmaf(a0, bv, part[0][r]);
                    part[1][r] = fmaf(a1, bv, part[1][r]);
                    part[2][r] = fmaf(a2, bv, part[2][r]);
                    part[3][r] = fmaf(a3, bv, part[3][r]);
                }
            }
            s++;
        }
        #pragma unroll
        for (int i = 0; i < 4; i++)
            #pragma unroll
            for (int r = 0; r < 12; r++)
                acc[i][r] = fmaf(pwv[i], part[i][r], acc[i][r]);
    }

    // epilogue: relu(acc + bias_eff), coalesced-ish float4 stores
    float be[12];
    #pragma unroll
    for (int r = 0; r < 12; r++) be[r] = g_be[d*A_ + r];

    #pragma unroll
    for (int i = 0; i < 4; i++) {
        int p = p0 + 4*gp + i;
        float* op = out + ((size_t)(b*C2_ + d)*P_ + p) * A_;
        float v[12];
        #pragma unroll
        for (int r = 0; r < 12; r++) v[r] = fmaxf(acc[i][r] + be[r], 0.0f);
        reinterpret_cast<float4*>(op)[0] = make_float4(v[0], v[1], v[2],  v[3]);
        reinterpret_cast<float4*>(op)[1] = make_float4(v[4], v[5], v[6],  v[7]);
        reinterpret_cast<float4*>(op)[2] = make_float4(v[8], v[9], v[10], v[11]);
    }
}

// -------- launcher --------
extern "C" void kernel_launch(void* const* d_in, const int* in_sizes, int n_in,
                              void* d_out, int out_size) {
    const int*   nbr     = (const int*)  d_in[0];   // (B,P,24)
    const float* vert    = (const float*)d_in[1];   // (B,P,3)
    const float* fm      = (const float*)d_in[2];   // (B,C1,K,P,A)
    const float* W       = (const float*)d_in[3];   // (C2,C1,36)
    const float* bias    = (const float*)d_in[4];   // (C2,5)
    const float* kpw     = (const float*)d_in[5];   // (C2,36)
    const float* vs      = (const float*)d_in[6];   // (12,3)
    const int*   idx_map = (const int*)  d_in[7];   // (156,)
    const int*   tivr    = (const int*)  d_in[8];   // (A,K)
    const int*   tir     = (const int*)  d_in[9];   // (A,A)
    const int*   lvl     = (const int*)  d_in[10];  // (13,)
    float*       out     = (float*)d_out;           // (B,C2,P,A)

    prep_small<<<1, 512>>>(kpw, vs, idx_map, bias, lvl, tivr);

    int wt_elems = K_*CA_*NDR_;
    prep_wt<<<(wt_elems + 255)/256, 256>>>(W, kpw, idx_map, tivr, tir);

    mean_dir_kernel<<<(B_*P_ + 255)/256, 256>>>(nbr, vert);

    const int smem_bytes = (2*TP_*CA_ + 2*CC_*NDR_ + C2_*K_*3) * (int)sizeof(float); // ~197KB
    cudaFuncSetAttribute(main_kernel, cudaFuncAttributeMaxDynamicSharedMemorySize, smem_bytes);
    main_kernel<<<B_ * (P_/TP_), 256, smem_bytes>>>(fm, out);
}

// round 4
// speedup vs baseline: 3.0603x; 3.0603x over previous
#include <cuda_runtime.h>
#include <math.h>
#include <stdint.h>

#define B_   2
#define P_   8192
#define NB_  24
#define C1_  32
#define C2_  32
#define K_   13
#define A_   12
#define CA_  384

// smem float offsets
#define SA_F    0            // [2][128][28]  = 7168 floats
#define SB_F    7168         // [2][24][200]  = 9600 floats
#define SACC_F  16768        // [128][196]    = 25088 floats
#define SKPO_F  41856        // 1248
#define SBE_F   43104        // 384
#define SMEM_FLOATS 43488    // 173952 bytes

// ---------------- device scratch ----------------
__device__ __align__(16) float g_WT[K_*CA_*384];   // [k][ca][n_full], tf32-rounded (7.66MB)
__device__ __align__(16) float g_md[B_*P_*3];
__device__ __align__(16) float g_kpo[C2_*K_*3];    // [d][k][3]
__device__ __align__(16) float g_be[C2_*A_];       // [d][r]

// ---------------- helpers ----------------
__device__ __forceinline__ float tf32r(float x) {
    uint32_t u;
    asm("cvt.rna.tf32.f32 %0, %1;" : "=r"(u) : "f"(x));
    return __uint_as_float(u);
}
__device__ __forceinline__ uint32_t tf32u(float x) {
    uint32_t u;
    asm("cvt.rna.tf32.f32 %0, %1;" : "=r"(u) : "f"(x));
    return u;
}
__device__ __forceinline__ void cp16(void* dst, const void* src) {
    uint32_t a;
    asm("{ .reg .u64 t; cvta.to.shared.u64 t, %1; cvt.u32.u64 %0, t; }" : "=r"(a) : "l"(dst));
    asm volatile("cp.async.cg.shared.global [%0], [%1], 16;" :: "r"(a), "l"(src));
}
#define CP_COMMIT() asm volatile("cp.async.commit_group;" ::: "memory")
#define CP_WAIT1()  asm volatile("cp.async.wait_group 1;" ::: "memory")
#define CP_WAIT0()  asm volatile("cp.async.wait_group 0;" ::: "memory")

__device__ __forceinline__ void mma8(float* d, const uint32_t* a, uint32_t b0, uint32_t b1) {
    asm volatile(
        "mma.sync.aligned.m16n8k8.row.col.f32.tf32.tf32.f32 "
        "{%0,%1,%2,%3}, {%4,%5,%6,%7}, {%8,%9}, {%0,%1,%2,%3};"
        : "+f"(d[0]), "+f"(d[1]), "+f"(d[2]), "+f"(d[3])
        : "r"(a[0]), "r"(a[1]), "r"(a[2]), "r"(a[3]), "r"(b0), "r"(b1));
}

// ---------------- prep kernels ----------------
__global__ void prep_small(const float* __restrict__ kpw, const float* __restrict__ vs,
                           const int* __restrict__ idx_map, const float* __restrict__ bias,
                           const int* __restrict__ lvl, const int* __restrict__ tivr) {
    int tid = threadIdx.x;
    if (tid < C2_*K_) {
        int d = tid / K_, k = tid % K_;
        float s0 = 0.f, s1 = 0.f, s2 = 0.f;
        for (int a = 0; a < A_; a++) {
            float w = kpw[d*36 + idx_map[k*A_ + a]];
            s0 += w * vs[a*3+0]; s1 += w * vs[a*3+1]; s2 += w * vs[a*3+2];
        }
        float inv = 1.0f / fmaxf(sqrtf(s0*s0 + s1*s1 + s2*s2), 1e-12f);
        g_kpo[tid*3+0] = s0*inv; g_kpo[tid*3+1] = s1*inv; g_kpo[tid*3+2] = s2*inv;
    }
    if (tid < C2_*A_) {
        int d = tid / A_, r = tid % A_;
        float be = 0.f;
        for (int k = 0; k < K_; k++) be += bias[d*5 + lvl[tivr[r*K_ + k]]];
        g_be[tid] = be;
    }
}

__global__ void mean_dir_kernel(const int* __restrict__ nbr, const float* __restrict__ vert) {
    int t = blockIdx.x * blockDim.x + threadIdx.x;
    if (t >= B_*P_) return;
    int b = t / P_;
    float vx = vert[t*3+0], vy = vert[t*3+1], vz = vert[t*3+2];
    float mx = 0.f, my = 0.f, mz = 0.f;
    const int* np = nbr + (size_t)t * NB_;
    const float* vb = vert + (size_t)b * P_ * 3;
    #pragma unroll 4
    for (int n = 0; n < NB_; n++) {
        int q = np[n];
        float dx = vb[q*3+0] - vx, dy = vb[q*3+1] - vy, dz = vb[q*3+2] - vz;
        float inv = 1.0f / fmaxf(sqrtf(dx*dx + dy*dy + dz*dz), 1e-12f);
        mx += dx*inv; my += dy*inv; mz += dz*inv;
    }
    const float s = 1.0f / (float)NB_;
    g_md[t*3+0] = mx*s; g_md[t*3+1] = my*s; g_md[t*3+2] = mz*s;
}

// WT[d,c,k,a,r] -> g_WT[k][ca=c*12+a][n_full], tf32-rounded.
// n_full = (d/16)*192 + ((d/4)%4)*48 + r*4 + (d%4)
__global__ void prep_wt(const float* __restrict__ W, const float* __restrict__ kpw,
                        const int* __restrict__ idx_map, const int* __restrict__ tivr,
                        const int* __restrict__ tir) {
    int idx = blockIdx.x * 256 + threadIdx.x;
    if (idx >= K_*CA_*384) return;
    int k   = idx / (CA_*384);
    int rem = idx - k*(CA_*384);
    int ca  = rem / 384;
    int nf  = rem - ca*384;
    int d = (nf/192)*16 + ((nf%192)/48)*4 + (nf & 3);
    int r = (nf % 48) >> 2;
    int c = ca / A_, a = ca - c*A_;
    int m = idx_map[tivr[r*K_ + k]*A_ + tir[r*A_ + a]];
    g_WT[idx] = tf32r(W[(d*C1_ + c)*36 + m] * kpw[d*36 + m]);
}

// ---------------- main kernel ----------------
// grid = 256 = b(2) * ptile(64) * nh(2); block = 512 (16 warps: wm = wid&3, wn = wid>>2)
__global__ void __launch_bounds__(512, 1)
main_kernel(const float* __restrict__ fm, float* __restrict__ out) {
    extern __shared__ float sm[];
    float* sA   = sm + SA_F;
    float* sB   = sm + SB_F;
    float* sAcc = sm + SACC_F;
    float* sKpo = sm + SKPO_F;
    float* sBe  = sm + SBE_F;

    const int tid  = threadIdx.x;
    const int wid  = tid >> 5;
    const int lane = tid & 31;
    const int wm = wid & 3, wn = wid >> 2;
    const int g = lane >> 2, t = lane & 3;
    const int nh = blockIdx.x & 1;
    const int pt = blockIdx.x >> 1;
    const int b  = pt >> 6;
    const int p0 = (pt & 63) << 7;

    for (int i = tid; i < 128*196; i += 512) sAcc[i] = 0.f;
    for (int i = tid; i < C2_*K_*3; i += 512) sKpo[i] = g_kpo[i];
    if (tid < C2_*A_) sBe[tid] = g_be[tid];

    // mean_dir for this thread's 4 rows
    float md[2][2][3];
    #pragma unroll
    for (int mf = 0; mf < 2; mf++)
        #pragma unroll
        for (int h = 0; h < 2; h++) {
            int p = p0 + wm*32 + mf*16 + g + 8*h;
            const float* mp = g_md + ((size_t)b*P_ + p)*3;
            md[mf][h][0] = mp[0]; md[mf][h][1] = mp[1]; md[mf][h][2] = mp[2];
        }

    float part[2][6][4];
    #pragma unroll
    for (int mf = 0; mf < 2; mf++)
        #pragma unroll
        for (int nf = 0; nf < 6; nf++)
            #pragma unroll
            for (int c = 0; c < 4; c++) part[mf][nf][c] = 0.f;

    // chunk loader: s = k*16 + ch; chunk = 24 ca (2 c's); stage = s&1
    auto load_chunk = [&](int s) {
        const int k = s >> 4, ch = s & 15;
        float* Ad = sA + (s & 1)*3584;
        float* Bd = sB + (s & 1)*4800;
        // A: 768 16B-units: (cl, p, aq)
        #pragma unroll
        for (int j = 0; j < 2; j++) {
            int u = tid + 512*j;
            if (u < 768) {
                int cl = u / 384;
                int rm = u - cl*384;
                int p  = rm / 3;
                int aq = rm - p*3;
                const float* src = fm + ((((size_t)b*C1_ + ch*2 + cl)*K_ + k)*P_ + p0 + p)*A_ + aq*4;
                cp16(Ad + p*28 + cl*12 + aq*4, src);
            }
        }
        // B: 1152 16B-units: (ca, jj)
        #pragma unroll
        for (int j = 0; j < 3; j++) {
            int u = tid + 512*j;
            if (u < 1152) {
                int ca = u / 48;
                int jj = u - ca*48;
                const float* src = g_WT + ((size_t)k*CA_ + ch*24 + ca)*384 + nh*192 + jj*4;
                cp16(Bd + ca*200 + jj*4, src);
            }
        }
    };

    __syncthreads();           // acc/kpo/be visible before anyone reads; also before cp.async reuse
    load_chunk(0); CP_COMMIT();

    for (int s = 0; s < K_*16; s++) {
        if (s + 1 < K_*16) { load_chunk(s + 1); CP_COMMIT(); CP_WAIT1(); }
        else               { CP_WAIT0(); }
        __syncthreads();

        const float* Ast = sA + (s & 1)*3584;
        const float* Bst = sB + (s & 1)*4800;

        #pragma unroll
        for (int cs = 0; cs < 3; cs++) {
            const float* Ab = Ast + (wm*32)*28 + cs*8;
            const float* Bb = Bst + (cs*8)*200 + wn*48;
            uint32_t a[2][4];
            #pragma unroll
            for (int mf = 0; mf < 2; mf++) {
                int r0 = mf*16 + g;
                a[mf][0] = tf32u(Ab[r0*28 + t]);
                a[mf][1] = tf32u(Ab[(r0+8)*28 + t]);
                a[mf][2] = tf32u(Ab[r0*28 + t + 4]);
                a[mf][3] = tf32u(Ab[(r0+8)*28 + t + 4]);
            }
            #pragma unroll
            for (int nf = 0; nf < 6; nf++) {
                uint32_t b0 = __float_as_uint(Bb[t*200 + nf*8 + g]);
                uint32_t b1 = __float_as_uint(Bb[(t+4)*200 + nf*8 + g]);
                mma8(part[0][nf], a[0], b0, b1);
                mma8(part[1][nf], a[1], b0, b1);
            }
        }

        if ((s & 15) == 15) {
            // per-k epilogue: acc += pw * part
            const int k = s >> 4;
            const int d0 = nh*16 + wn*4 + (t & 1)*2;
            float kp[2][3];
            #pragma unroll
            for (int e = 0; e < 2; e++) {
                const float* q = sKpo + ((d0 + e)*K_ + k)*3;
                kp[e][0] = q[0]; kp[e][1] = q[1]; kp[e][2] = q[2];
            }
            float pw[2][2][2];
            #pragma unroll
            for (int mf = 0; mf < 2; mf++)
                #pragma unroll
                for (int h = 0; h < 2; h++)
                    #pragma unroll
                    for (int e = 0; e < 2; e++) {
                        float v = md[mf][h][0]*kp[e][0] + md[mf][h][1]*kp[e][1] + md[mf][h][2]*kp[e][2];
                        pw[mf][h][e] = fmaxf(v, 0.f);
                    }
            #pragma unroll
            for (int mf = 0; mf < 2; mf++)
                #pragma unroll
                for (int nf = 0; nf < 6; nf++)
                    #pragma unroll
                    for (int c = 0; c < 4; c++) {
                        int h = c >> 1, e = c & 1;
                        int row = wm*32 + mf*16 + g + 8*h;
                        int col = wn*48 + nf*8 + 2*t + e;
                        sAcc[row*196 + col] += pw[mf][h][e] * part[mf][nf][c];
                        part[mf][nf][c] = 0.f;
                    }
        }
        __syncthreads();
    }

    // coalesced store: thread -> 4 (d,p) pairs, each 12 contiguous floats
    #pragma unroll
    for (int i = 0; i < 4; i++) {
        int pair = i*512 + tid;
        int p  = pair & 127;
        int dl = pair >> 7;           // 0..15
        int d  = nh*16 + dl;
        const float* ar = sAcc + p*196 + (dl >> 2)*48 + (dl & 3);
        float* op = out + (((size_t)b*C2_ + d)*P_ + p0 + p)*A_;
        float v[12];
        #pragma unroll
        for (int r = 0; r < 12; r++)
            v[r] = fmaxf(ar[r*4] + sBe[d*A_ + r], 0.f);
        reinterpret_cast<float4*>(op)[0] = make_float4(v[0], v[1], v[2],  v[3]);
        reinterpret_cast<float4*>(op)[1] = make_float4(v[4], v[5], v[6],  v[7]);
        reinterpret_cast<float4*>(op)[2] = make_float4(v[8], v[9], v[10], v[11]);
    }
}

// ---------------- launcher ----------------
extern "C" void kernel_launch(void* const* d_in, const int* in_sizes, int n_in,
                              void* d_out, int out_size) {
    const int*   nbr     = (const int*)  d_in[0];
    const float* vert    = (const float*)d_in[1];
    const float* fm      = (const float*)d_in[2];
    const float* W       = (const float*)d_in[3];
    const float* bias    = (const float*)d_in[4];
    const float* kpw     = (const float*)d_in[5];
    const float* vs      = (const float*)d_in[6];
    const int*   idx_map = (const int*)  d_in[7];
    const int*   tivr    = (const int*)  d_in[8];
    const int*   tir     = (const int*)  d_in[9];
    const int*   lvl     = (const int*)  d_in[10];
    float*       out     = (float*)d_out;

    prep_small<<<1, 512>>>(kpw, vs, idx_map, bias, lvl, tivr);
    prep_wt<<<(K_*CA_*384 + 255)/256, 256>>>(W, kpw, idx_map, tivr, tir);
    mean_dir_kernel<<<(B_*P_ + 255)/256, 256>>>(nbr, vert);

    const int smem_bytes = SMEM_FLOATS * (int)sizeof(float);   // 173952
    cudaFuncSetAttribute(main_kernel, cudaFuncAttributeMaxDynamicSharedMemorySize, smem_bytes);
    main_kernel<<<256, 512, smem_bytes>>>(fm, out);
}

// round 5
// speedup vs baseline: 3.1663x; 1.0346x over previous
#include <cuda_runtime.h>
#include <math.h>
#include <stdint.h>

#define B_   2
#define P_   8192
#define NB_  24
#define C1_  32
#define C2_  32
#define K_   13
#define A_   12
#define CA_  384
#define NCHK_ 16                 // 24-ca chunks per k
#define STEPS_ (K_*NCHK_)        // 208

// smem float offsets
#define SA_F    0                // 4 stages x 128x24      = 12288
#define SB_F    12288            // 4 stages x 4608        = 18432
#define SACC_F  30720            // 128 x 196              = 25088
#define SKPO_F  55808            // 1248
#define SMEM_FLOATS 57056        // 228224 bytes

// ---------------- device scratch ----------------
// g_WT: [k][nh][ch][wn][cs][q][lane][4]  (1,916,928 floats, tf32-rounded)
__device__ __align__(16) float g_WT[(size_t)K_*2*NCHK_*4608];
__device__ __align__(16) float g_md[B_*P_*3];
__device__ __align__(16) float g_kpo[C2_*K_*3];
__device__ __align__(16) float g_be[C2_*A_];

// ---------------- helpers ----------------
__device__ __forceinline__ float tf32r(float x) {
    uint32_t u; asm("cvt.rna.tf32.f32 %0, %1;" : "=r"(u) : "f"(x));
    return __uint_as_float(u);
}
__device__ __forceinline__ uint32_t tf32u(float x) {
    uint32_t u; asm("cvt.rna.tf32.f32 %0, %1;" : "=r"(u) : "f"(x));
    return u;
}
__device__ __forceinline__ void cp16(void* dst, const void* src) {
    uint32_t a;
    asm("{ .reg .u64 t; cvta.to.shared.u64 t, %1; cvt.u32.u64 %0, t; }" : "=r"(a) : "l"(dst));
    asm volatile("cp.async.cg.shared.global [%0], [%1], 16;" :: "r"(a), "l"(src));
}
#define CP_COMMIT() asm volatile("cp.async.commit_group;" ::: "memory")
#define CP_WAIT2()  asm volatile("cp.async.wait_group 2;" ::: "memory")

__device__ __forceinline__ void mma8(float* d, const uint32_t* a, uint32_t b0, uint32_t b1) {
    asm volatile(
        "mma.sync.aligned.m16n8k8.row.col.f32.tf32.tf32.f32 "
        "{%0,%1,%2,%3}, {%4,%5,%6,%7}, {%8,%9}, {%0,%1,%2,%3};"
        : "+f"(d[0]), "+f"(d[1]), "+f"(d[2]), "+f"(d[3])
        : "r"(a[0]), "r"(a[1]), "r"(a[2]), "r"(a[3]), "r"(b0), "r"(b1));
}

// ---------------- prep kernels ----------------
__global__ void prep_small(const float* __restrict__ kpw, const float* __restrict__ vs,
                           const int* __restrict__ idx_map, const float* __restrict__ bias,
                           const int* __restrict__ lvl, const int* __restrict__ tivr) {
    int tid = threadIdx.x;
    if (tid < C2_*K_) {
        int d = tid / K_, k = tid % K_;
        float s0 = 0.f, s1 = 0.f, s2 = 0.f;
        for (int a = 0; a < A_; a++) {
            float w = kpw[d*36 + idx_map[k*A_ + a]];
            s0 += w * vs[a*3+0]; s1 += w * vs[a*3+1]; s2 += w * vs[a*3+2];
        }
        float inv = 1.0f / fmaxf(sqrtf(s0*s0 + s1*s1 + s2*s2), 1e-12f);
        g_kpo[tid*3+0] = s0*inv; g_kpo[tid*3+1] = s1*inv; g_kpo[tid*3+2] = s2*inv;
    }
    if (tid < C2_*A_) {
        int d = tid / A_, r = tid % A_;
        float be = 0.f;
        for (int k = 0; k < K_; k++) be += bias[d*5 + lvl[tivr[r*K_ + k]]];
        g_be[tid] = be;
    }
}

__global__ void mean_dir_kernel(const int* __restrict__ nbr, const float* __restrict__ vert) {
    int t = blockIdx.x * blockDim.x + threadIdx.x;
    if (t >= B_*P_) return;
    int b = t / P_;
    float vx = vert[t*3+0], vy = vert[t*3+1], vz = vert[t*3+2];
    float mx = 0.f, my = 0.f, mz = 0.f;
    const int* np = nbr + (size_t)t * NB_;
    const float* vb = vert + (size_t)b * P_ * 3;
    #pragma unroll 4
    for (int n = 0; n < NB_; n++) {
        int q = np[n];
        float dx = vb[q*3+0] - vx, dy = vb[q*3+1] - vy, dz = vb[q*3+2] - vz;
        float inv = 1.0f / fmaxf(sqrtf(dx*dx + dy*dy + dz*dz), 1e-12f);
        mx += dx*inv; my += dy*inv; mz += dz*inv;
    }
    const float s = 1.0f / (float)NB_;
    g_md[t*3+0] = mx*s; g_md[t*3+1] = my*s; g_md[t*3+2] = mz*s;
}

// WT -> g_WT[k][nh][ch][wn][cs][q][lane][e], tf32-rounded.
// logical-k permutation: physical j = 2t + (e&1); logical n = nf*8 + g, nf = 2q + (e>>1)
__global__ void prep_wt(const float* __restrict__ W, const float* __restrict__ kpw,
                        const int* __restrict__ idx_map, const int* __restrict__ tivr,
                        const int* __restrict__ tir) {
    int idx = blockIdx.x * 256 + threadIdx.x;
    if (idx >= K_*2*NCHK_*4608) return;
    int e    = idx & 3;  int u = idx >> 2;
    int lane = u & 31;   u >>= 5;
    int q    = u % 3;    u /= 3;
    int cs   = u % 3;    u /= 3;
    int wn   = u & 3;    u >>= 2;
    int ch   = u & 15;   u >>= 4;
    int nh   = u & 1;
    int k    = u >> 1;
    int g = lane >> 2, t = lane & 3;
    int nf = 2*q + (e >> 1);
    int ca = ch*24 + cs*8 + 2*t + (e & 1);
    int c = ca / A_, a = ca - c*A_;
    int n192 = wn*48 + nf*8 + g;
    int d = nh*16 + wn*4 + (g & 3);
    int r = (n192 % 48) >> 2;
    int m = idx_map[tivr[r*K_ + k]*A_ + tir[r*A_ + a]];
    g_WT[idx] = tf32r(W[(d*C1_ + c)*36 + m] * kpw[d*36 + m]);
}

// ---------------- main kernel ----------------
// grid = 256 = b(2) x ptile(64) x nh(2); block = 512 (wm = wid&3, wn = wid>>2)
__global__ void __launch_bounds__(512, 1)
main_kernel(const float* __restrict__ fm, float* __restrict__ out) {
    extern __shared__ float sm[];
    float* sA   = sm + SA_F;
    float* sB   = sm + SB_F;
    float* sAcc = sm + SACC_F;
    float* sKpo = sm + SKPO_F;

    const int tid  = threadIdx.x;
    const int wid  = tid >> 5;
    const int lane = tid & 31;
    const int wm = wid & 3, wn = wid >> 2;
    const int g = lane >> 2, t = lane & 3;
    const int nh = blockIdx.x & 1;
    const int pt = blockIdx.x >> 1;
    const int b  = pt >> 6;
    const int p0 = (pt & 63) << 7;

    for (int i = tid; i < 128*196; i += 512) sAcc[i] = 0.f;
    for (int i = tid; i < C2_*K_*3; i += 512) sKpo[i] = g_kpo[i];

    float md[2][2][3];
    #pragma unroll
    for (int mf = 0; mf < 2; mf++)
        #pragma unroll
        for (int h = 0; h < 2; h++) {
            int p = p0 + wm*32 + mf*16 + g + 8*h;
            const float* mp = g_md + ((size_t)b*P_ + p)*3;
            md[mf][h][0] = mp[0]; md[mf][h][1] = mp[1]; md[mf][h][2] = mp[2];
        }

    float part[2][6][4];
    #pragma unroll
    for (int mf = 0; mf < 2; mf++)
        #pragma unroll
        for (int nf = 0; nf < 6; nf++)
            #pragma unroll
            for (int c = 0; c < 4; c++) part[mf][nf][c] = 0.f;

    // loader: s in [0, 208); stage = s & 3
    auto load_chunk = [&](int s) {
        const int k = s >> 4, ch = s & 15;
        const int st = s & 3;
        float* Ad = sA + st*3072;
        // A: 768 16B units (cl, p, aq); row stride 24 floats
        #pragma unroll
        for (int j = 0; j < 2; j++) {
            int u = tid + 512*j;
            if (u < 768) {
                int cl = u / 384;
                int rm = u - cl*384;
                int p  = rm / 3;
                int aq = rm - p*3;
                const float* src = fm + ((((size_t)b*C1_ + ch*2 + cl)*K_ + k)*P_ + p0 + p)*A_ + aq*4;
                cp16(Ad + p*24 + cl*12 + aq*4, src);
            }
        }
        // B: 1152 16B units, dense
        float* Bd = sB + st*4608;
        const float* bsrc = g_WT + ((size_t)(k*2 + nh)*NCHK_ + ch)*4608;
        #pragma unroll
        for (int j = 0; j < 3; j++) {
            int u = tid + 512*j;
            if (u < 1152) cp16(Bd + u*4, bsrc + u*4);
        }
    };

    load_chunk(0); CP_COMMIT();
    load_chunk(1); CP_COMMIT();
    load_chunk(2); CP_COMMIT();

    const int arow = (wm*32 + g)*12;       // float2-unit row base (mf0)

    for (int k = 0; k < K_; k++) {
        #pragma unroll 1
        for (int ch = 0; ch < NCHK_; ch++) {
            const int s = k*NCHK_ + ch;
            CP_WAIT2();
            __syncthreads();

            const int st = s & 3;
            const float2* A2 = (const float2*)(sA + st*3072);
            const float4* B4 = (const float4*)(sB + st*4608);

            #pragma unroll
            for (int cs = 0; cs < 3; cs++) {
                uint32_t a[2][4];
                #pragma unroll
                for (int mf = 0; mf < 2; mf++) {
                    float2 f0 = A2[arow + mf*192 + cs*4 + t];        // rows g,   cols (2t,2t+1)
                    float2 f1 = A2[arow + mf*192 + 96 + cs*4 + t];   // rows g+8
                    a[mf][0] = tf32u(f0.x); a[mf][2] = tf32u(f0.y);
                    a[mf][1] = tf32u(f1.x); a[mf][3] = tf32u(f1.y);
                }
                const float4* Bq = B4 + (wn*3 + cs)*96 + lane;
                float4 q0 = Bq[0], q1 = Bq[32], q2 = Bq[64];
                mma8(part[0][0], a[0], __float_as_uint(q0.x), __float_as_uint(q0.y));
                mma8(part[1][0], a[1], __float_as_uint(q0.x), __float_as_uint(q0.y));
                mma8(part[0][1], a[0], __float_as_uint(q0.z), __float_as_uint(q0.w));
                mma8(part[1][1], a[1], __float_as_uint(q0.z), __float_as_uint(q0.w));
                mma8(part[0][2], a[0], __float_as_uint(q1.x), __float_as_uint(q1.y));
                mma8(part[1][2], a[1], __float_as_uint(q1.x), __float_as_uint(q1.y));
                mma8(part[0][3], a[0], __float_as_uint(q1.z), __float_as_uint(q1.w));
                mma8(part[1][3], a[1], __float_as_uint(q1.z), __float_as_uint(q1.w));
                mma8(part[0][4], a[0], __float_as_uint(q2.x), __float_as_uint(q2.y));
                mma8(part[1][4], a[1], __float_as_uint(q2.x), __float_as_uint(q2.y));
                mma8(part[0][5], a[0], __float_as_uint(q2.z), __float_as_uint(q2.w));
                mma8(part[1][5], a[1], __float_as_uint(q2.z), __float_as_uint(q2.w));
            }

            // prefetch s+3 into stage (s+3)&3 (safe: after barrier, distance 4)
            if (s + 3 < STEPS_) load_chunk(s + 3);
            CP_COMMIT();
        }

        // per-k fold: acc += pw * part
        {
            const int d0 = nh*16 + wn*4 + (t & 1)*2;
            float kp[2][3];
            #pragma unroll
            for (int e = 0; e < 2; e++) {
                const float* q = sKpo + ((d0 + e)*K_ + k)*3;
                kp[e][0] = q[0]; kp[e][1] = q[1]; kp[e][2] = q[2];
            }
            float pw[2][2][2];
            #pragma unroll
            for (int mf = 0; mf < 2; mf++)
                #pragma unroll
                for (int h = 0; h < 2; h++)
                    #pragma unroll
                    for (int e = 0; e < 2; e++)
                        pw[mf][h][e] = fmaxf(md[mf][h][0]*kp[e][0] + md[mf][h][1]*kp[e][1]
                                           + md[mf][h][2]*kp[e][2], 0.f);
            #pragma unroll
            for (int mf = 0; mf < 2; mf++)
                #pragma unroll
                for (int nf = 0; nf < 6; nf++)
                    #pragma unroll
                    for (int c = 0; c < 4; c++) {
                        int h = c >> 1, e = c & 1;
                        int row = wm*32 + mf*16 + g + 8*h;
                        int col = wn*48 + nf*8 + 2*t + e;
                        sAcc[row*196 + col] += pw[mf][h][e] * part[mf][nf][c];
                        part[mf][nf][c] = 0.f;
                    }
        }
    }

    __syncthreads();

    // coalesced store: thread -> 4 (d,p) pairs, 12 contiguous floats each
    #pragma unroll
    for (int i = 0; i < 4; i++) {
        int pair = i*512 + tid;
        int p  = pair & 127;
        int dl = pair >> 7;
        int d  = nh*16 + dl;
        const float* ar = sAcc + p*196 + (dl >> 2)*48 + (dl & 3);
        float* op = out + (((size_t)b*C2_ + d)*P_ + p0 + p)*A_;
        float v[12];
        #pragma unroll
        for (int r = 0; r < 12; r++)
            v[r] = fmaxf(ar[r*4] + g_be[d*A_ + r], 0.f);
        reinterpret_cast<float4*>(op)[0] = make_float4(v[0], v[1], v[2],  v[3]);
        reinterpret_cast<float4*>(op)[1] = make_float4(v[4], v[5], v[6],  v[7]);
        reinterpret_cast<float4*>(op)[2] = make_float4(v[8], v[9], v[10], v[11]);
    }
}

// ---------------- launcher ----------------
extern "C" void kernel_launch(void* const* d_in, const int* in_sizes, int n_in,
                              void* d_out, int out_size) {
    const int*   nbr     = (const int*)  d_in[0];
    const float* vert    = (const float*)d_in[1];
    const float* fm      = (const float*)d_in[2];
    const float* W       = (const float*)d_in[3];
    const float* bias    = (const float*)d_in[4];
    const float* kpw     = (const float*)d_in[5];
    const float* vs      = (const float*)d_in[6];
    const int*   idx_map = (const int*)  d_in[7];
    const int*   tivr    = (const int*)  d_in[8];
    const int*   tir     = (const int*)  d_in[9];
    const int*   lvl     = (const int*)  d_in[10];
    float*       out     = (float*)d_out;

    prep_small<<<1, 512>>>(kpw, vs, idx_map, bias, lvl, tivr);
    prep_wt<<<(K_*2*NCHK_*4608 + 255)/256, 256>>>(W, kpw, idx_map, tivr, tir);
    mean_dir_kernel<<<(B_*P_ + 255)/256, 256>>>(nbr, vert);

    const int smem_bytes = SMEM_FLOATS * (int)sizeof(float);   // 228224
    cudaFuncSetAttribute(main_kernel, cudaFuncAttributeMaxDynamicSharedMemorySize, smem_bytes);
    main_kernel<<<256, 512, smem_bytes>>>(fm, out);
}